// round 7
// baseline (speedup 1.0000x reference)
#include <cuda_runtime.h>
#include <cuda_bf16.h>
#include <cstdint>
#include <cstddef>

#define BATCH 4
#define CCH 256
#define NTOK 4096
#define GROUPS 32
#define CPG 8
#define EPSV 1e-6f

typedef __nv_bfloat16 bf16;

// ---------------- scratch ----------------
__device__ uint4 g_xnb4 [(size_t)BATCH * CCH * NTOK / 8];
__device__ uint4 g_qkvb4[(size_t)3 * BATCH * CCH * NTOK / 8];
__device__ uint4 g_ob4  [(size_t)BATCH * CCH * NTOK / 8];
__device__ uint4 g_attnb4[(size_t)BATCH * NTOK * NTOK / 8];
__device__ uint4 g_wb4[4][CCH * CCH / 8];
__device__ float g_biasqkv[3 * CCH];
__device__ float g_psum[(size_t)BATCH * NTOK * 16];
__device__ float g_invs[BATCH * NTOK];
__device__ float g_gnstat[BATCH * GROUPS * 4 * 2];   // per-quarter {s, s2}

// ---------------- asm helpers ----------------
__device__ __forceinline__ uint32_t smem_u32(const void* p) {
    uint32_t a;
    asm("{ .reg .u64 t; cvta.to.shared.u64 t, %1; cvt.u32.u64 %0, t; }"
        : "=r"(a) : "l"(p));
    return a;
}
__device__ __forceinline__ void ldsm4(uint32_t* r, uint32_t a) {
    asm volatile("ldmatrix.sync.aligned.m8n8.x4.shared.b16 {%0,%1,%2,%3}, [%4];"
        : "=r"(r[0]), "=r"(r[1]), "=r"(r[2]), "=r"(r[3]) : "r"(a));
}
__device__ __forceinline__ void ldsm4t(uint32_t* r, uint32_t a) {
    asm volatile("ldmatrix.sync.aligned.m8n8.x4.trans.shared.b16 {%0,%1,%2,%3}, [%4];"
        : "=r"(r[0]), "=r"(r[1]), "=r"(r[2]), "=r"(r[3]) : "r"(a));
}
__device__ __forceinline__ void mma16(float* c, const uint32_t* a,
                                      uint32_t b0, uint32_t b1) {
    asm volatile(
        "mma.sync.aligned.m16n8k16.row.col.f32.bf16.bf16.f32 "
        "{%0,%1,%2,%3}, {%4,%5,%6,%7}, {%8,%9}, {%0,%1,%2,%3};"
        : "+f"(c[0]), "+f"(c[1]), "+f"(c[2]), "+f"(c[3])
        : "r"(a[0]), "r"(a[1]), "r"(a[2]), "r"(a[3]), "r"(b0), "r"(b1));
}
__device__ __forceinline__ void cp16(uint32_t d, const void* s) {
    asm volatile("cp.async.cg.shared.global [%0], [%1], 16;" :: "r"(d), "l"(s));
}

// ---------------------------------------------------------------------------
// Weight fp32 -> bf16 (packed) + bias packing
// ---------------------------------------------------------------------------
__global__ void convw_kernel(const float* wq, const float* wk,
                             const float* wv, const float* wo,
                             const float* bq, const float* bk, const float* bv,
                             bf16* w0, bf16* w1, bf16* w2, bf16* w3,
                             float* biasqkv) {
    int i = blockIdx.x * 256 + threadIdx.x;
    w0[i] = __float2bfloat16(wq[i]);
    w1[i] = __float2bfloat16(wk[i]);
    w2[i] = __float2bfloat16(wv[i]);
    w3[i] = __float2bfloat16(wo[i]);
    if (i < CCH) {
        biasqkv[i]           = bq[i];
        biasqkv[CCH + i]     = bk[i];
        biasqkv[2 * CCH + i] = bv[i];
    }
}

// ---------------------------------------------------------------------------
// GroupNorm stats: 512 blocks, each reduces a quarter-group (8192 floats)
// ---------------------------------------------------------------------------
__global__ void gn_stats_kernel(const float* __restrict__ x,
                                float* __restrict__ stat) {
    const float4* xp = (const float4*)(x + (size_t)blockIdx.x * 8192);
    int tid = threadIdx.x;
    float s = 0.f, s2 = 0.f;
    #pragma unroll
    for (int i = 0; i < 8; i++) {
        float4 v = xp[tid + i * 256];
        s  += v.x + v.y + v.z + v.w;
        s2 += v.x*v.x + v.y*v.y + v.z*v.z + v.w*v.w;
    }
    __shared__ float sh0[256], sh1[256];
    sh0[tid] = s; sh1[tid] = s2;
    __syncthreads();
    for (int off = 128; off > 0; off >>= 1) {
        if (tid < off) { sh0[tid] += sh0[tid + off]; sh1[tid] += sh1[tid + off]; }
        __syncthreads();
    }
    if (tid == 0) {
        stat[blockIdx.x * 2]     = sh0[0];
        stat[blockIdx.x * 2 + 1] = sh1[0];
    }
}

// ---------------------------------------------------------------------------
// GroupNorm apply: 512 blocks, each one quarter-group (8192 floats), bf16 out
// ---------------------------------------------------------------------------
__global__ void gn_apply_kernel(const float* __restrict__ x,
                                const float* __restrict__ stat,
                                const float* __restrict__ w,
                                const float* __restrict__ b,
                                bf16* __restrict__ xnb) {
    int blk = blockIdx.x;               // 512 blocks of 8192 floats
    int bg  = blk >> 2;                 // batch*group index (0..127)
    int grp = bg % GROUPS;
    float s  = stat[bg * 8 + 0] + stat[bg * 8 + 2] +
               stat[bg * 8 + 4] + stat[bg * 8 + 6];
    float s2 = stat[bg * 8 + 1] + stat[bg * 8 + 3] +
               stat[bg * 8 + 5] + stat[bg * 8 + 7];
    const float nall = (float)(CPG * NTOK);
    float mean = s / nall;
    float var  = s2 / nall - mean * mean;
    float rstd = rsqrtf(var + EPSV);

    size_t base = (size_t)blk * 8192;
    const float4* xp = (const float4*)(x + base);
    bf16* op = xnb + base;
    int tid = threadIdx.x;
    #pragma unroll
    for (int i = 0; i < 8; i++) {
        int idx = tid + i * 256;                 // f4 index within 2048
        int ch = grp * CPG + (int)(((blk & 3) * 8192 + idx * 4) / NTOK);
        float sc = rstd * w[ch];
        float sb = b[ch] - mean * sc;
        float4 v = xp[idx];
        __nv_bfloat162 h0 = __floats2bfloat162_rn(v.x * sc + sb, v.y * sc + sb);
        __nv_bfloat162 h1 = __floats2bfloat162_rn(v.z * sc + sb, v.w * sc + sb);
        uint2 u;
        u.x = *(uint32_t*)&h0; u.y = *(uint32_t*)&h1;
        *(uint2*)(op + idx * 4) = u;
    }
}

// ---------------------------------------------------------------------------
// Row-sum reduce + invert: 16384 rows x 16 partials
// ---------------------------------------------------------------------------
__global__ void rowinv_kernel(const float* __restrict__ psum,
                              float* __restrict__ invs) {
    int i = blockIdx.x * 256 + threadIdx.x;
    const float4* p = (const float4*)(psum + (size_t)i * 16);
    float4 a = p[0], b = p[1], c = p[2], d = p[3];
    float s = a.x+a.y+a.z+a.w + b.x+b.y+b.z+b.w + c.x+c.y+c.z+c.w + d.x+d.y+d.z+d.w;
    invs[i] = 1.f / s;
}

// ---------------------------------------------------------------------------
// bf16 GEMM, CTA tile 128x256, BK=64, 256 threads = 8 warps @ 64x64.
// 3-stage cp.async ring, ldmatrix + mma.m16n8k16, fp32 accumulate (128 regs).
// AST 0: A [m][k'] k-cont -> smem [m][k] stride 72
// AST 1: A [k'][m] m-cont -> smem [k][m] stride 136 (ldmatrix.trans)
// BST 0: B [n][k'] k-cont -> smem [n][k] stride 72
// BST 1: B [k'][n] n-cont -> smem [k][n] stride 264 (ldmatrix.trans)
// OUTF 0: bf16 (+bias, QKV-packed); 1: fp32 + bias + resid;
// OUTF 2: exp epilogue + psum; 3: scale by invs[n]
// ---------------------------------------------------------------------------
#define ABYTES 18432u
#define STAGEB 55296u
#define SMEM_DYN (3 * 55296)

template <int AST, int BST, int OUTF, int QKV>
__global__ void __launch_bounds__(256, 1)
bgemm(const bf16* __restrict__ A, const bf16* __restrict__ B,
      const float* __restrict__ bias, const float* __restrict__ resid,
      void* __restrict__ Cv, float* __restrict__ psum,
      const float* __restrict__ invs,
      int K, int lda, int ldb, int ldc,
      size_t sA, size_t sB, size_t sC, size_t sR, float alpha) {
    extern __shared__ __align__(16) char smem[];
    const int bz = blockIdx.z;

    int M0;
    size_t cext = 0;
    if (QKV) {
        int mat = blockIdx.y >> 1;
        A    += (size_t)mat * (CCH * CCH);
        bias += mat * CCH;
        cext  = (size_t)mat * BATCH * (size_t)CCH * NTOK;
        M0 = (blockIdx.y & 1) * 128;
    } else {
        M0 = blockIdx.y * 128;
    }
    A += (size_t)bz * sA;
    B += (size_t)bz * sB;

    const int N0 = blockIdx.x * 256;
    const int tid  = threadIdx.x;
    const int lane = tid & 31;
    const int wid  = tid >> 5;
    const int wm = wid >> 2;        // 0..1 -> 64 rows
    const int wn = wid & 3;         // 0..3 -> 64 cols
    const int g  = lane >> 2;
    const int t  = lane & 3;
    const int l7  = lane & 7;
    const int l15 = lane & 15;
    const int b3 = (lane >> 3) & 1;
    const int b4 = (lane >> 4) & 1;

    const uint32_t smem_u = smem_u32(smem);

    float acc[4][8][4];
    #pragma unroll
    for (int i = 0; i < 4; i++)
        #pragma unroll
        for (int j = 0; j < 8; j++)
            #pragma unroll
            for (int q = 0; q < 4; q++) acc[i][j][q] = 0.f;

    const int KT = K >> 6;

    auto stage = [&](int kt, int buf) {
        uint32_t ab = smem_u + (uint32_t)buf * STAGEB;
        uint32_t bbs = ab + ABYTES;
        int k0 = kt << 6;
        #pragma unroll
        for (int i = 0; i < 4; i++) {           // A: 128x64
            int c = tid + i * 256;
            if (AST == 0) {
                int m = c >> 3, kc = c & 7;
                cp16(ab + (uint32_t)(m * 72 + kc * 8) * 2,
                     A + (size_t)(M0 + m) * lda + k0 + kc * 8);
            } else {
                int k = c >> 4, mc = c & 15;
                cp16(ab + (uint32_t)(k * 136 + mc * 8) * 2,
                     A + (size_t)(k0 + k) * lda + M0 + mc * 8);
            }
        }
        #pragma unroll
        for (int i = 0; i < 8; i++) {           // B: 256x64 or 64x256
            int c = tid + i * 256;
            if (BST == 0) {
                int n = c >> 3, kc = c & 7;
                cp16(bbs + (uint32_t)(n * 72 + kc * 8) * 2,
                     B + (size_t)(N0 + n) * ldb + k0 + kc * 8);
            } else {
                int k = c >> 5, nc = c & 31;
                cp16(bbs + (uint32_t)(k * 264 + nc * 8) * 2,
                     B + (size_t)(k0 + k) * ldb + N0 + nc * 8);
            }
        }
    };

    stage(0, 0);
    asm volatile("cp.async.commit_group;" ::: "memory");
    stage(1, 1);
    asm volatile("cp.async.commit_group;" ::: "memory");

    for (int kt = 0; kt < KT; kt++) {
        asm volatile("cp.async.wait_group 1;" ::: "memory");
        __syncthreads();
        if (kt + 2 < KT) stage(kt + 2, (kt + 2) % 3);
        asm volatile("cp.async.commit_group;" ::: "memory");

        uint32_t ab = smem_u + (uint32_t)(kt % 3) * STAGEB;
        uint32_t bbs = ab + ABYTES;

        #pragma unroll
        for (int ks = 0; ks < 4; ks++) {
            uint32_t af[4][4];
            #pragma unroll
            for (int i = 0; i < 4; i++) {
                if (AST == 0) {
                    uint32_t addr = ab + 2u * (uint32_t)(
                        (wm * 64 + i * 16 + l15) * 72 + ks * 16 + b4 * 8);
                    ldsm4(af[i], addr);
                } else {
                    uint32_t addr = ab + 2u * (uint32_t)(
                        (ks * 16 + b4 * 8 + l7) * 136 + wm * 64 + i * 16 + b3 * 8);
                    ldsm4t(af[i], addr);
                }
            }
            uint32_t bfr[4][4];
            #pragma unroll
            for (int j2 = 0; j2 < 4; j2++) {
                int nb = wn * 64 + j2 * 16;
                if (BST == 0) {
                    uint32_t addr = bbs + 2u * (uint32_t)(
                        (nb + b4 * 8 + l7) * 72 + ks * 16 + b3 * 8);
                    ldsm4(bfr[j2], addr);
                } else {
                    uint32_t addr = bbs + 2u * (uint32_t)(
                        (ks * 16 + b3 * 8 + l7) * 264 + nb + b4 * 8);
                    ldsm4t(bfr[j2], addr);
                }
            }
            #pragma unroll
            for (int j2 = 0; j2 < 4; j2++) {
                #pragma unroll
                for (int i = 0; i < 4; i++) {
                    mma16(acc[i][2*j2],     af[i], bfr[j2][0], bfr[j2][1]);
                    mma16(acc[i][2*j2 + 1], af[i], bfr[j2][2], bfr[j2][3]);
                }
            }
        }
    }

    // -------- epilogues --------
    if (OUTF == 0) {
        bf16* C = (bf16*)Cv + cext + (size_t)bz * sC;
        #pragma unroll
        for (int i = 0; i < 4; i++) {
            int m = M0 + wm * 64 + i * 16 + g;
            float bm0 = bias[m];
            float bm1 = bias[m + 8];
            #pragma unroll
            for (int j = 0; j < 8; j++) {
                int n = N0 + wn * 64 + j * 8 + 2 * t;
                *(__nv_bfloat162*)(C + (size_t)m * ldc + n) =
                    __floats2bfloat162_rn(acc[i][j][0] + bm0, acc[i][j][1] + bm0);
                *(__nv_bfloat162*)(C + (size_t)(m + 8) * ldc + n) =
                    __floats2bfloat162_rn(acc[i][j][2] + bm1, acc[i][j][3] + bm1);
            }
        }
    } else if (OUTF == 1) {
        float* C = (float*)Cv + (size_t)bz * sC;
        const float* R = resid + (size_t)bz * sR;
        #pragma unroll
        for (int i = 0; i < 4; i++) {
            int m = M0 + wm * 64 + i * 16 + g;
            float bm0 = bias[m];
            float bm1 = bias[m + 8];
            #pragma unroll
            for (int j = 0; j < 8; j++) {
                int n = N0 + wn * 64 + j * 8 + 2 * t;
                float2 r0 = *(const float2*)(R + (size_t)m * ldc + n);
                float2 r1 = *(const float2*)(R + (size_t)(m + 8) * ldc + n);
                float2 v0, v1;
                v0.x = acc[i][j][0] + bm0 + r0.x;
                v0.y = acc[i][j][1] + bm0 + r0.y;
                v1.x = acc[i][j][2] + bm1 + r1.x;
                v1.y = acc[i][j][3] + bm1 + r1.y;
                *(float2*)(C + (size_t)m * ldc + n)       = v0;
                *(float2*)(C + (size_t)(m + 8) * ldc + n) = v1;
            }
        }
    } else if (OUTF == 2) {
        bf16* C = (bf16*)Cv + (size_t)bz * sC;
        float* ps = (float*)smem;            // [4][128]
        __syncthreads();
        #pragma unroll
        for (int i = 0; i < 4; i++) {
            int m = M0 + wm * 64 + i * 16 + g;
            float sr0 = 0.f, sr1 = 0.f;
            #pragma unroll
            for (int j = 0; j < 8; j++) {
                int n = N0 + wn * 64 + j * 8 + 2 * t;
                float e0 = __expf(acc[i][j][0] * alpha);
                float e1 = __expf(acc[i][j][1] * alpha);
                float e2 = __expf(acc[i][j][2] * alpha);
                float e3 = __expf(acc[i][j][3] * alpha);
                sr0 += e0 + e1;
                sr1 += e2 + e3;
                *(__nv_bfloat162*)(C + (size_t)m * ldc + n) =
                    __floats2bfloat162_rn(e0, e1);
                *(__nv_bfloat162*)(C + (size_t)(m + 8) * ldc + n) =
                    __floats2bfloat162_rn(e2, e3);
            }
            sr0 += __shfl_xor_sync(0xffffffffu, sr0, 1);
            sr0 += __shfl_xor_sync(0xffffffffu, sr0, 2);
            sr1 += __shfl_xor_sync(0xffffffffu, sr1, 1);
            sr1 += __shfl_xor_sync(0xffffffffu, sr1, 2);
            if (t == 0) {
                int r = wm * 64 + i * 16 + g;
                ps[wn * 128 + r]     = sr0;
                ps[wn * 128 + r + 8] = sr1;
            }
        }
        __syncthreads();
        if (tid < 128) {
            float tot = ps[tid] + ps[128 + tid] + ps[256 + tid] + ps[384 + tid];
            psum[((size_t)bz * NTOK + M0 + tid) * 16 + blockIdx.x] = tot;
        }
    } else {
        bf16* C = (bf16*)Cv + (size_t)bz * sC;
        const float* iv = invs + (size_t)bz * NTOK;
        #pragma unroll
        for (int i = 0; i < 4; i++) {
            int m = M0 + wm * 64 + i * 16 + g;
            #pragma unroll
            for (int j = 0; j < 8; j++) {
                int n = N0 + wn * 64 + j * 8 + 2 * t;
                float2 w2 = *(const float2*)(iv + n);
                *(__nv_bfloat162*)(C + (size_t)m * ldc + n) =
                    __floats2bfloat162_rn(acc[i][j][0] * w2.x, acc[i][j][1] * w2.y);
                *(__nv_bfloat162*)(C + (size_t)(m + 8) * ldc + n) =
                    __floats2bfloat162_rn(acc[i][j][2] * w2.x, acc[i][j][3] * w2.y);
            }
        }
    }
}

// ---------------------------------------------------------------------------
extern "C" void kernel_launch(void* const* d_in, const int* in_sizes, int n_in,
                              void* d_out, int out_size) {
    const float* x    = (const float*)d_in[0];
    const float* gn_w = (const float*)d_in[1];
    const float* gn_b = (const float*)d_in[2];
    const float* wq   = (const float*)d_in[3];
    const float* bq   = (const float*)d_in[4];
    const float* wk   = (const float*)d_in[5];
    const float* bk   = (const float*)d_in[6];
    const float* wv   = (const float*)d_in[7];
    const float* bv   = (const float*)d_in[8];
    const float* wo   = (const float*)d_in[9];
    const float* bo   = (const float*)d_in[10];
    float* out = (float*)d_out;

    void *p_xn, *p_qkv, *p_o, *p_attn, *p_w, *p_bias, *p_psum, *p_inv, *p_stat;
    cudaGetSymbolAddress(&p_xn,   g_xnb4);
    cudaGetSymbolAddress(&p_qkv,  g_qkvb4);
    cudaGetSymbolAddress(&p_o,    g_ob4);
    cudaGetSymbolAddress(&p_attn, g_attnb4);
    cudaGetSymbolAddress(&p_w,    g_wb4);
    cudaGetSymbolAddress(&p_bias, g_biasqkv);
    cudaGetSymbolAddress(&p_psum, g_psum);
    cudaGetSymbolAddress(&p_inv,  g_invs);
    cudaGetSymbolAddress(&p_stat, g_gnstat);

    bf16* xnb  = (bf16*)p_xn;
    bf16* qkvb = (bf16*)p_qkv;
    bf16* atb  = (bf16*)p_attn;
    bf16* ob   = (bf16*)p_o;
    bf16* wqb  = (bf16*)p_w;
    bf16* wob  = wqb + 3 * CCH * CCH;
    float* biasqkv = (float*)p_bias;
    float* psum = (float*)p_psum;
    float* invs = (float*)p_inv;
    float* stat = (float*)p_stat;

    const size_t SBb = (size_t)CCH * NTOK;
    const size_t SAb = (size_t)NTOK * NTOK;
    bf16* qb = qkvb;
    bf16* kb = qkvb + BATCH * SBb;
    bf16* vb = qkvb + 2 * BATCH * SBb;
    const float scale = 0.0625f;

    cudaFuncSetAttribute(bgemm<0,1,0,1>, cudaFuncAttributeMaxDynamicSharedMemorySize, SMEM_DYN);
    cudaFuncSetAttribute(bgemm<1,1,2,0>, cudaFuncAttributeMaxDynamicSharedMemorySize, SMEM_DYN);
    cudaFuncSetAttribute(bgemm<0,0,3,0>, cudaFuncAttributeMaxDynamicSharedMemorySize, SMEM_DYN);
    cudaFuncSetAttribute(bgemm<0,1,1,0>, cudaFuncAttributeMaxDynamicSharedMemorySize, SMEM_DYN);

    // 0) convert+pack weights / biases
    convw_kernel<<<256, 256>>>(wq, wk, wv, wo, bq, bk, bv,
                               wqb, wqb + CCH*CCH, wqb + 2*CCH*CCH, wob, biasqkv);

    // 1) GroupNorm (stats + apply), bf16 out — 512 quarter-group blocks each
    gn_stats_kernel<<<BATCH * GROUPS * 4, 256>>>(x, stat);
    gn_apply_kernel<<<BATCH * GROUPS * 4, 256>>>(x, stat, gn_w, gn_b, xnb);

    // 2) fused QKV projection
    bgemm<0,1,0,1><<<dim3(NTOK/256, 6, BATCH), 256, SMEM_DYN>>>(
        wqb, xnb, biasqkv, nullptr, qkvb, nullptr, nullptr,
        CCH, CCH, NTOK, NTOK, 0, SBb, SBb, 0, 1.0f);

    // 3) scores + exp + partial row sums
    bgemm<1,1,2,0><<<dim3(NTOK/256, NTOK/128, BATCH), 256, SMEM_DYN>>>(
        qb, kb, nullptr, nullptr, atb, psum, nullptr,
        CCH, NTOK, NTOK, NTOK, SBb, SBb, SAb, 0, scale);

    // 4) reduce + invert row sums
    rowinv_kernel<<<BATCH * NTOK / 256, 256>>>(psum, invs);

    // 5) PV with normalization epilogue
    bgemm<0,0,3,0><<<dim3(NTOK/256, CCH/128, BATCH), 256, SMEM_DYN>>>(
        vb, atb, nullptr, nullptr, ob, nullptr, invs,
        NTOK, NTOK, NTOK, NTOK, SBb, SAb, SBb, 0, 1.0f);

    // 6) output projection + bias + residual (fp32 out)
    bgemm<0,1,1,0><<<dim3(NTOK/256, CCH/128, BATCH), 256, SMEM_DYN>>>(
        wob, ob, bo, x, out, nullptr, nullptr,
        CCH, CCH, NTOK, NTOK, 0, SBb, SBb, SBb, 1.0f);
}

// round 8
// speedup vs baseline: 1.0391x; 1.0391x over previous
#include <cuda_runtime.h>
#include <cuda_bf16.h>
#include <cstdint>
#include <cstddef>

#define BATCH 4
#define CCH 256
#define NTOK 4096
#define GROUPS 32
#define CPG 8
#define EPSV 1e-6f

typedef __nv_bfloat16 bf16;

// ---------------- scratch ----------------
__device__ uint4 g_xnb4 [(size_t)BATCH * CCH * NTOK / 8];
__device__ uint4 g_qkvb4[(size_t)3 * BATCH * CCH * NTOK / 8];
__device__ uint4 g_ob4  [(size_t)BATCH * CCH * NTOK / 8];
__device__ uint4 g_attnb4[(size_t)BATCH * NTOK * NTOK / 8];
__device__ uint4 g_wb4[4][CCH * CCH / 8];
__device__ float g_biasqkv[3 * CCH];
__device__ float g_psum[(size_t)BATCH * NTOK * 32];
__device__ float g_invs[BATCH * NTOK];
__device__ float g_gnstat[BATCH * GROUPS * 4 * 2];

// ---------------- asm helpers ----------------
__device__ __forceinline__ uint32_t smem_u32(const void* p) {
    uint32_t a;
    asm("{ .reg .u64 t; cvta.to.shared.u64 t, %1; cvt.u32.u64 %0, t; }"
        : "=r"(a) : "l"(p));
    return a;
}
__device__ __forceinline__ void ldsm4(uint32_t* r, uint32_t a) {
    asm volatile("ldmatrix.sync.aligned.m8n8.x4.shared.b16 {%0,%1,%2,%3}, [%4];"
        : "=r"(r[0]), "=r"(r[1]), "=r"(r[2]), "=r"(r[3]) : "r"(a));
}
__device__ __forceinline__ void ldsm4t(uint32_t* r, uint32_t a) {
    asm volatile("ldmatrix.sync.aligned.m8n8.x4.trans.shared.b16 {%0,%1,%2,%3}, [%4];"
        : "=r"(r[0]), "=r"(r[1]), "=r"(r[2]), "=r"(r[3]) : "r"(a));
}
__device__ __forceinline__ void mma16(float* c, const uint32_t* a,
                                      uint32_t b0, uint32_t b1) {
    asm volatile(
        "mma.sync.aligned.m16n8k16.row.col.f32.bf16.bf16.f32 "
        "{%0,%1,%2,%3}, {%4,%5,%6,%7}, {%8,%9}, {%0,%1,%2,%3};"
        : "+f"(c[0]), "+f"(c[1]), "+f"(c[2]), "+f"(c[3])
        : "r"(a[0]), "r"(a[1]), "r"(a[2]), "r"(a[3]), "r"(b0), "r"(b1));
}
__device__ __forceinline__ void cp16(uint32_t d, const void* s) {
    asm volatile("cp.async.cg.shared.global [%0], [%1], 16;" :: "r"(d), "l"(s));
}

// ---------------------------------------------------------------------------
__global__ void convw_kernel(const float* wq, const float* wk,
                             const float* wv, const float* wo,
                             const float* bq, const float* bk, const float* bv,
                             bf16* w0, bf16* w1, bf16* w2, bf16* w3,
                             float* biasqkv) {
    int i = blockIdx.x * 256 + threadIdx.x;
    w0[i] = __float2bfloat16(wq[i]);
    w1[i] = __float2bfloat16(wk[i]);
    w2[i] = __float2bfloat16(wv[i]);
    w3[i] = __float2bfloat16(wo[i]);
    if (i < CCH) {
        biasqkv[i]           = bq[i];
        biasqkv[CCH + i]     = bk[i];
        biasqkv[2 * CCH + i] = bv[i];
    }
}

// ---------------------------------------------------------------------------
// GroupNorm stats: 512 blocks, each reduces a quarter-group (8192 floats)
// ---------------------------------------------------------------------------
__global__ void gn_stats_kernel(const float* __restrict__ x,
                                float* __restrict__ stat) {
    const float4* xp = (const float4*)(x + (size_t)blockIdx.x * 8192);
    int tid = threadIdx.x;
    float s = 0.f, s2 = 0.f;
    #pragma unroll
    for (int i = 0; i < 8; i++) {
        float4 v = xp[tid + i * 256];
        s  += v.x + v.y + v.z + v.w;
        s2 += v.x*v.x + v.y*v.y + v.z*v.z + v.w*v.w;
    }
    __shared__ float sh0[256], sh1[256];
    sh0[tid] = s; sh1[tid] = s2;
    __syncthreads();
    for (int off = 128; off > 0; off >>= 1) {
        if (tid < off) { sh0[tid] += sh0[tid + off]; sh1[tid] += sh1[tid + off]; }
        __syncthreads();
    }
    if (tid == 0) {
        stat[blockIdx.x * 2]     = sh0[0];
        stat[blockIdx.x * 2 + 1] = sh1[0];
    }
}

// ---------------------------------------------------------------------------
// GroupNorm apply: 512 blocks, each one quarter-group (8192 floats)
// ---------------------------------------------------------------------------
__global__ void gn_apply_kernel(const float* __restrict__ x,
                                const float* __restrict__ stat,
                                const float* __restrict__ w,
                                const float* __restrict__ b,
                                bf16* __restrict__ xnb) {
    int blk = blockIdx.x;
    int bg  = blk >> 2;
    int grp = bg % GROUPS;
    float s  = stat[bg * 8 + 0] + stat[bg * 8 + 2] +
               stat[bg * 8 + 4] + stat[bg * 8 + 6];
    float s2 = stat[bg * 8 + 1] + stat[bg * 8 + 3] +
               stat[bg * 8 + 5] + stat[bg * 8 + 7];
    const float nall = (float)(CPG * NTOK);
    float mean = s / nall;
    float var  = s2 / nall - mean * mean;
    float rstd = rsqrtf(var + EPSV);

    size_t base = (size_t)blk * 8192;
    const float4* xp = (const float4*)(x + base);
    bf16* op = xnb + base;
    int tid = threadIdx.x;
    #pragma unroll
    for (int i = 0; i < 8; i++) {
        int idx = tid + i * 256;
        int ch = grp * CPG + (int)(((blk & 3) * 8192 + idx * 4) / NTOK);
        float sc = rstd * w[ch];
        float sb = b[ch] - mean * sc;
        float4 v = xp[idx];
        __nv_bfloat162 h0 = __floats2bfloat162_rn(v.x * sc + sb, v.y * sc + sb);
        __nv_bfloat162 h1 = __floats2bfloat162_rn(v.z * sc + sb, v.w * sc + sb);
        uint2 u;
        u.x = *(uint32_t*)&h0; u.y = *(uint32_t*)&h1;
        *(uint2*)(op + idx * 4) = u;
    }
}

// ---------------------------------------------------------------------------
// Row-sum reduce + invert: 16384 rows x 32 partials
// ---------------------------------------------------------------------------
__global__ void rowinv_kernel(const float* __restrict__ psum,
                              float* __restrict__ invs) {
    int i = blockIdx.x * 256 + threadIdx.x;
    const float4* p = (const float4*)(psum + (size_t)i * 32);
    float s = 0.f;
    #pragma unroll
    for (int j = 0; j < 8; j++) {
        float4 a = p[j];
        s += a.x + a.y + a.z + a.w;
    }
    invs[i] = 1.f / s;
}

// ---------------------------------------------------------------------------
// bf16 GEMM, CTA tile 128x128, BK=64, 128 threads = 4 warps @ 64x64.
// 3-stage cp.async ring, one __syncthreads per k-tile, 2 CTAs/SM.
// AST 0: A [m][k'] k-cont -> smem [m][k] stride 72
// AST 1: A [k'][m] m-cont -> smem [k][m] stride 136 (ldmatrix.trans)
// BST 0: B [n][k'] k-cont -> smem [n][k] stride 72
// BST 1: B [k'][n] n-cont -> smem [k][n] stride 136 (ldmatrix.trans)
// OUTF 0: bf16 (+bias, QKV-packed); 1: fp32 + bias + resid;
// OUTF 2: exp epilogue + psum; 3: scale by invs[n]
// ---------------------------------------------------------------------------
#define ABYTES 18432u
#define STAGEB 36864u
#define SMEM_DYN (3 * 36864)

template <int AST, int BST, int OUTF, int QKV>
__global__ void __launch_bounds__(128, 2)
bgemm(const bf16* __restrict__ A, const bf16* __restrict__ B,
      const float* __restrict__ bias, const float* __restrict__ resid,
      void* __restrict__ Cv, float* __restrict__ psum,
      const float* __restrict__ invs,
      int K, int lda, int ldb, int ldc,
      size_t sA, size_t sB, size_t sC, size_t sR, float alpha) {
    extern __shared__ __align__(16) char smem[];
    const int bz = blockIdx.z;

    int M0;
    size_t cext = 0;
    if (QKV) {
        int mat = blockIdx.y >> 1;
        A    += (size_t)mat * (CCH * CCH);
        bias += mat * CCH;
        cext  = (size_t)mat * BATCH * (size_t)CCH * NTOK;
        M0 = (blockIdx.y & 1) * 128;
    } else {
        M0 = blockIdx.y * 128;
    }
    A += (size_t)bz * sA;
    B += (size_t)bz * sB;

    const int N0 = blockIdx.x * 128;
    const int tid  = threadIdx.x;
    const int lane = tid & 31;
    const int wid  = tid >> 5;
    const int wm = wid >> 1;        // 0..1 -> 64 rows
    const int wn = wid & 1;         // 0..1 -> 64 cols
    const int g  = lane >> 2;
    const int t  = lane & 3;
    const int l7  = lane & 7;
    const int l15 = lane & 15;
    const int b3 = (lane >> 3) & 1;
    const int b4 = (lane >> 4) & 1;

    const uint32_t smem_u = smem_u32(smem);

    float acc[4][8][4];
    #pragma unroll
    for (int i = 0; i < 4; i++)
        #pragma unroll
        for (int j = 0; j < 8; j++)
            #pragma unroll
            for (int q = 0; q < 4; q++) acc[i][j][q] = 0.f;

    const int KT = K >> 6;

    auto stage = [&](int kt, int buf) {
        uint32_t ab = smem_u + (uint32_t)buf * STAGEB;
        uint32_t bbs = ab + ABYTES;
        int k0 = kt << 6;
        #pragma unroll
        for (int i = 0; i < 8; i++) {           // A: 128x64
            int c = tid + i * 128;
            if (AST == 0) {
                int m = c >> 3, kc = c & 7;
                cp16(ab + (uint32_t)(m * 72 + kc * 8) * 2,
                     A + (size_t)(M0 + m) * lda + k0 + kc * 8);
            } else {
                int k = c >> 4, mc = c & 15;
                cp16(ab + (uint32_t)(k * 136 + mc * 8) * 2,
                     A + (size_t)(k0 + k) * lda + M0 + mc * 8);
            }
        }
        #pragma unroll
        for (int i = 0; i < 8; i++) {           // B: 128x64 or 64x128
            int c = tid + i * 128;
            if (BST == 0) {
                int n = c >> 3, kc = c & 7;
                cp16(bbs + (uint32_t)(n * 72 + kc * 8) * 2,
                     B + (size_t)(N0 + n) * ldb + k0 + kc * 8);
            } else {
                int k = c >> 4, nc = c & 15;
                cp16(bbs + (uint32_t)(k * 136 + nc * 8) * 2,
                     B + (size_t)(k0 + k) * ldb + N0 + nc * 8);
            }
        }
    };

    stage(0, 0);
    asm volatile("cp.async.commit_group;" ::: "memory");
    stage(1, 1);
    asm volatile("cp.async.commit_group;" ::: "memory");

    for (int kt = 0; kt < KT; kt++) {
        asm volatile("cp.async.wait_group 1;" ::: "memory");
        __syncthreads();
        if (kt + 2 < KT) stage(kt + 2, (kt + 2) % 3);
        asm volatile("cp.async.commit_group;" ::: "memory");

        uint32_t ab = smem_u + (uint32_t)(kt % 3) * STAGEB;
        uint32_t bbs = ab + ABYTES;

        #pragma unroll
        for (int ks = 0; ks < 4; ks++) {
            uint32_t af[4][4];
            #pragma unroll
            for (int i = 0; i < 4; i++) {
                if (AST == 0) {
                    uint32_t addr = ab + 2u * (uint32_t)(
                        (wm * 64 + i * 16 + l15) * 72 + ks * 16 + b4 * 8);
                    ldsm4(af[i], addr);
                } else {
                    uint32_t addr = ab + 2u * (uint32_t)(
                        (ks * 16 + b4 * 8 + l7) * 136 + wm * 64 + i * 16 + b3 * 8);
                    ldsm4t(af[i], addr);
                }
            }
            uint32_t bfr[4][4];
            #pragma unroll
            for (int j2 = 0; j2 < 4; j2++) {
                int nb = wn * 64 + j2 * 16;
                if (BST == 0) {
                    uint32_t addr = bbs + 2u * (uint32_t)(
                        (nb + b4 * 8 + l7) * 72 + ks * 16 + b3 * 8);
                    ldsm4(bfr[j2], addr);
                } else {
                    uint32_t addr = bbs + 2u * (uint32_t)(
                        (ks * 16 + b3 * 8 + l7) * 136 + nb + b4 * 8);
                    ldsm4t(bfr[j2], addr);
                }
            }
            #pragma unroll
            for (int j2 = 0; j2 < 4; j2++) {
                #pragma unroll
                for (int i = 0; i < 4; i++) {
                    mma16(acc[i][2*j2],     af[i], bfr[j2][0], bfr[j2][1]);
                    mma16(acc[i][2*j2 + 1], af[i], bfr[j2][2], bfr[j2][3]);
                }
            }
        }
    }

    // -------- epilogues --------
    if (OUTF == 0) {
        bf16* C = (bf16*)Cv + cext + (size_t)bz * sC;
        #pragma unroll
        for (int i = 0; i < 4; i++) {
            int m = M0 + wm * 64 + i * 16 + g;
            float bm0 = bias[m];
            float bm1 = bias[m + 8];
            #pragma unroll
            for (int j = 0; j < 8; j++) {
                int n = N0 + wn * 64 + j * 8 + 2 * t;
                *(__nv_bfloat162*)(C + (size_t)m * ldc + n) =
                    __floats2bfloat162_rn(acc[i][j][0] + bm0, acc[i][j][1] + bm0);
                *(__nv_bfloat162*)(C + (size_t)(m + 8) * ldc + n) =
                    __floats2bfloat162_rn(acc[i][j][2] + bm1, acc[i][j][3] + bm1);
            }
        }
    } else if (OUTF == 1) {
        float* C = (float*)Cv + (size_t)bz * sC;
        const float* R = resid + (size_t)bz * sR;
        #pragma unroll
        for (int i = 0; i < 4; i++) {
            int m = M0 + wm * 64 + i * 16 + g;
            float bm0 = bias[m];
            float bm1 = bias[m + 8];
            #pragma unroll
            for (int j = 0; j < 8; j++) {
                int n = N0 + wn * 64 + j * 8 + 2 * t;
                float2 r0 = *(const float2*)(R + (size_t)m * ldc + n);
                float2 r1 = *(const float2*)(R + (size_t)(m + 8) * ldc + n);
                float2 v0, v1;
                v0.x = acc[i][j][0] + bm0 + r0.x;
                v0.y = acc[i][j][1] + bm0 + r0.y;
                v1.x = acc[i][j][2] + bm1 + r1.x;
                v1.y = acc[i][j][3] + bm1 + r1.y;
                *(float2*)(C + (size_t)m * ldc + n)       = v0;
                *(float2*)(C + (size_t)(m + 8) * ldc + n) = v1;
            }
        }
    } else if (OUTF == 2) {
        bf16* C = (bf16*)Cv + (size_t)bz * sC;
        float* ps = (float*)smem;            // [2][128]
        __syncthreads();
        #pragma unroll
        for (int i = 0; i < 4; i++) {
            int m = M0 + wm * 64 + i * 16 + g;
            float sr0 = 0.f, sr1 = 0.f;
            #pragma unroll
            for (int j = 0; j < 8; j++) {
                int n = N0 + wn * 64 + j * 8 + 2 * t;
                float e0 = __expf(acc[i][j][0] * alpha);
                float e1 = __expf(acc[i][j][1] * alpha);
                float e2 = __expf(acc[i][j][2] * alpha);
                float e3 = __expf(acc[i][j][3] * alpha);
                sr0 += e0 + e1;
                sr1 += e2 + e3;
                *(__nv_bfloat162*)(C + (size_t)m * ldc + n) =
                    __floats2bfloat162_rn(e0, e1);
                *(__nv_bfloat162*)(C + (size_t)(m + 8) * ldc + n) =
                    __floats2bfloat162_rn(e2, e3);
            }
            sr0 += __shfl_xor_sync(0xffffffffu, sr0, 1);
            sr0 += __shfl_xor_sync(0xffffffffu, sr0, 2);
            sr1 += __shfl_xor_sync(0xffffffffu, sr1, 1);
            sr1 += __shfl_xor_sync(0xffffffffu, sr1, 2);
            if (t == 0) {
                int r = wm * 64 + i * 16 + g;
                ps[wn * 128 + r]     = sr0;
                ps[wn * 128 + r + 8] = sr1;
            }
        }
        __syncthreads();
        // 128 threads cover 128 rows
        float tot = ps[tid] + ps[128 + tid];
        psum[((size_t)bz * NTOK + M0 + tid) * 32 + blockIdx.x] = tot;
    } else {
        bf16* C = (bf16*)Cv + (size_t)bz * sC;
        const float* iv = invs + (size_t)bz * NTOK;
        #pragma unroll
        for (int i = 0; i < 4; i++) {
            int m = M0 + wm * 64 + i * 16 + g;
            #pragma unroll
            for (int j = 0; j < 8; j++) {
                int n = N0 + wn * 64 + j * 8 + 2 * t;
                float2 w2 = *(const float2*)(iv + n);
                *(__nv_bfloat162*)(C + (size_t)m * ldc + n) =
                    __floats2bfloat162_rn(acc[i][j][0] * w2.x, acc[i][j][1] * w2.y);
                *(__nv_bfloat162*)(C + (size_t)(m + 8) * ldc + n) =
                    __floats2bfloat162_rn(acc[i][j][2] * w2.x, acc[i][j][3] * w2.y);
            }
        }
    }
}

// ---------------------------------------------------------------------------
extern "C" void kernel_launch(void* const* d_in, const int* in_sizes, int n_in,
                              void* d_out, int out_size) {
    const float* x    = (const float*)d_in[0];
    const float* gn_w = (const float*)d_in[1];
    const float* gn_b = (const float*)d_in[2];
    const float* wq   = (const float*)d_in[3];
    const float* bq   = (const float*)d_in[4];
    const float* wk   = (const float*)d_in[5];
    const float* bk   = (const float*)d_in[6];
    const float* wv   = (const float*)d_in[7];
    const float* bv   = (const float*)d_in[8];
    const float* wo   = (const float*)d_in[9];
    const float* bo   = (const float*)d_in[10];
    float* out = (float*)d_out;

    void *p_xn, *p_qkv, *p_o, *p_attn, *p_w, *p_bias, *p_psum, *p_inv, *p_stat;
    cudaGetSymbolAddress(&p_xn,   g_xnb4);
    cudaGetSymbolAddress(&p_qkv,  g_qkvb4);
    cudaGetSymbolAddress(&p_o,    g_ob4);
    cudaGetSymbolAddress(&p_attn, g_attnb4);
    cudaGetSymbolAddress(&p_w,    g_wb4);
    cudaGetSymbolAddress(&p_bias, g_biasqkv);
    cudaGetSymbolAddress(&p_psum, g_psum);
    cudaGetSymbolAddress(&p_inv,  g_invs);
    cudaGetSymbolAddress(&p_stat, g_gnstat);

    bf16* xnb  = (bf16*)p_xn;
    bf16* qkvb = (bf16*)p_qkv;
    bf16* atb  = (bf16*)p_attn;
    bf16* ob   = (bf16*)p_o;
    bf16* wqb  = (bf16*)p_w;
    bf16* wob  = wqb + 3 * CCH * CCH;
    float* biasqkv = (float*)p_bias;
    float* psum = (float*)p_psum;
    float* invs = (float*)p_inv;
    float* stat = (float*)p_stat;

    const size_t SBb = (size_t)CCH * NTOK;
    const size_t SAb = (size_t)NTOK * NTOK;
    bf16* qb = qkvb;
    bf16* kb = qkvb + BATCH * SBb;
    bf16* vb = qkvb + 2 * BATCH * SBb;
    const float scale = 0.0625f;

    cudaFuncSetAttribute(bgemm<0,1,0,1>, cudaFuncAttributeMaxDynamicSharedMemorySize, SMEM_DYN);
    cudaFuncSetAttribute(bgemm<1,1,2,0>, cudaFuncAttributeMaxDynamicSharedMemorySize, SMEM_DYN);
    cudaFuncSetAttribute(bgemm<0,0,3,0>, cudaFuncAttributeMaxDynamicSharedMemorySize, SMEM_DYN);
    cudaFuncSetAttribute(bgemm<0,1,1,0>, cudaFuncAttributeMaxDynamicSharedMemorySize, SMEM_DYN);

    // 0) convert+pack weights / biases
    convw_kernel<<<256, 256>>>(wq, wk, wv, wo, bq, bk, bv,
                               wqb, wqb + CCH*CCH, wqb + 2*CCH*CCH, wob, biasqkv);

    // 1) GroupNorm (stats + apply), bf16 out
    gn_stats_kernel<<<BATCH * GROUPS * 4, 256>>>(x, stat);
    gn_apply_kernel<<<BATCH * GROUPS * 4, 256>>>(x, stat, gn_w, gn_b, xnb);

    // 2) fused QKV projection
    bgemm<0,1,0,1><<<dim3(NTOK/128, 6, BATCH), 128, SMEM_DYN>>>(
        wqb, xnb, biasqkv, nullptr, qkvb, nullptr, nullptr,
        CCH, CCH, NTOK, NTOK, 0, SBb, SBb, 0, 1.0f);

    // 3) scores + exp + partial row sums
    bgemm<1,1,2,0><<<dim3(NTOK/128, NTOK/128, BATCH), 128, SMEM_DYN>>>(
        qb, kb, nullptr, nullptr, atb, psum, nullptr,
        CCH, NTOK, NTOK, NTOK, SBb, SBb, SAb, 0, scale);

    // 4) reduce + invert row sums
    rowinv_kernel<<<BATCH * NTOK / 256, 256>>>(psum, invs);

    // 5) PV with normalization epilogue
    bgemm<0,0,3,0><<<dim3(NTOK/128, CCH/128, BATCH), 128, SMEM_DYN>>>(
        vb, atb, nullptr, nullptr, ob, nullptr, invs,
        NTOK, NTOK, NTOK, NTOK, SBb, SAb, SBb, 0, 1.0f);

    // 6) output projection + bias + residual (fp32 out)
    bgemm<0,1,1,0><<<dim3(NTOK/128, CCH/128, BATCH), 128, SMEM_DYN>>>(
        wob, ob, bo, x, out, nullptr, nullptr,
        CCH, CCH, NTOK, NTOK, 0, SBb, SBb, SBb, 1.0f);
}